// round 2
// baseline (speedup 1.0000x reference)
#include <cuda_runtime.h>
#include <math_constants.h>
#include <limits.h>

#define HW      16384
#define WDIM    128
#define KTOP    16
#define THREADS 256

__global__ __launch_bounds__(THREADS, 4)
void topk_l2_kernel(const float* __restrict__ x,
                    float* __restrict__ out_val,   // [rows, 16]
                    float* __restrict__ out_coor)  // [rows, 16, 2] numeric float
{
    const int row = blockIdx.x;
    const int tid = threadIdx.x;

    const float4* __restrict__ xp =
        reinterpret_cast<const float4*>(x + (size_t)row * HW);

    // ---- per-thread top-16 (sorted descending, ties -> smaller index) ----
    float vals[KTOP];
    int   idxs[KTOP];
#pragma unroll
    for (int i = 0; i < KTOP; i++) { vals[i] = -CUDART_INF_F; idxs[i] = INT_MAX; }

    float ss = 0.0f;

    auto insert = [&](float v, int id) {
        if (v > vals[KTOP - 1] || (v == vals[KTOP - 1] && id < idxs[KTOP - 1])) {
            float cv = v; int ci = id;
#pragma unroll
            for (int j = 0; j < KTOP; j++) {
                bool better = (cv > vals[j]) || (cv == vals[j] && ci < idxs[j]);
                if (better) {
                    float tv = vals[j]; int ti = idxs[j];
                    vals[j] = cv; idxs[j] = ci;
                    cv = tv; ci = ti;
                }
            }
        }
    };

    constexpr int NITER = HW / 4 / THREADS;   // 16
#pragma unroll 4
    for (int it = 0; it < NITER; it++) {
        int v4i = tid + it * THREADS;         // coalesced float4 stream
        float4 v = xp[v4i];
        ss += v.x * v.x;
        ss += v.y * v.y;
        ss += v.z * v.z;
        ss += v.w * v.w;
        int base = v4i * 4;
        insert(v.x, base + 0);
        insert(v.y, base + 1);
        insert(v.z, base + 2);
        insert(v.w, base + 3);
    }

    // ---- shared memory ----
    __shared__ float sval[THREADS * KTOP];
    __shared__ int   sidx[THREADS * KTOP];
    __shared__ float sss[THREADS];

#pragma unroll
    for (int i = 0; i < KTOP; i++) {
        sval[tid * KTOP + i] = vals[i];
        sidx[tid * KTOP + i] = idxs[i];
    }
    sss[tid] = ss;
    __syncthreads();

    // ---- sum-of-squares tree reduce (uniform barriers) ----
    for (int s = THREADS / 2; s > 0; s >>= 1) {
        float add = 0.0f;
        bool active = (tid < s);
        if (active) add = sss[tid] + sss[tid + s];
        __syncthreads();
        if (active) sss[tid] = add;
        __syncthreads();
    }

    // ---- tournament merge of sorted 16-lists (uniform barriers) ----
    for (int s = THREADS / 2; s >= 1; s >>= 1) {
        float ov[KTOP]; int oi[KTOP];
        bool active = (tid < s);
        if (active) {
            const float* av = &sval[tid * KTOP];
            const int*   ai = &sidx[tid * KTOP];
            const float* bv = &sval[(tid + s) * KTOP];
            const int*   bi = &sidx[(tid + s) * KTOP];
            int a = 0, b = 0;
#pragma unroll
            for (int k = 0; k < KTOP; k++) {
                float va = av[a], vb = bv[b];
                int   ia = ai[a], ib = bi[b];
                bool takeA = (va > vb) || (va == vb && ia < ib);
                if (takeA) { ov[k] = va; oi[k] = ia; a++; }
                else       { ov[k] = vb; oi[k] = ib; b++; }
            }
        }
        __syncthreads();
        if (active) {
#pragma unroll
            for (int k = 0; k < KTOP; k++) {
                sval[tid * KTOP + k] = ov[k];
                sidx[tid * KTOP + k] = oi[k];
            }
        }
        __syncthreads();
    }

    // ---- write outputs ----
    if (tid < KTOP) {
        float scale = rsqrtf(fmaxf(sss[0], 1e-12f));
        float v = sval[tid] * scale;
        int   id = sidx[tid];
        out_val[(size_t)row * KTOP + tid] = v;
        int h = id / WDIM;
        int w = id - h * WDIM;
        size_t cbase = ((size_t)row * KTOP + tid) * 2;
        out_coor[cbase + 0] = (float)h;
        out_coor[cbase + 1] = (float)w;
    }
}

extern "C" void kernel_launch(void* const* d_in, const int* in_sizes, int n_in,
                              void* d_out, int out_size)
{
    const float* x = (const float*)d_in[0];
    int n = in_sizes[0];              // 16*256*128*128
    int rows = n / HW;                // 4096

    float* out_val  = (float*)d_out;              // rows*16 values first
    float* out_coor = out_val + (size_t)rows * KTOP;  // then rows*16*2 coords

    topk_l2_kernel<<<rows, THREADS>>>(x, out_val, out_coor);
}

// round 3
// speedup vs baseline: 7.4842x; 7.4842x over previous
#include <cuda_runtime.h>
#include <math_constants.h>

#define HW      16384
#define WDIM    128
#define KTOP    16
#define THREADS 256
#define NITER   (HW / 4 / THREADS)   // 16 float4s per thread
#define CAP     512                  // candidate buffer (expected ~16-40 used)

// monotonic float <-> sortable-uint transform
__device__ __forceinline__ unsigned f2ord(float f) {
    unsigned u = __float_as_uint(f);
    return u ^ ((unsigned)((int)u >> 31) | 0x80000000u);
}
__device__ __forceinline__ float ord2f(unsigned s) {
    unsigned u = (s & 0x80000000u) ? (s ^ 0x80000000u) : ~s;
    return __uint_as_float(u);
}

__global__ void __launch_bounds__(THREADS)
topk_l2_kernel(const float* __restrict__ x,
               float* __restrict__ out_val,    // [rows,16]
               float* __restrict__ out_coor)   // [rows,16,2]
{
    const int row = blockIdx.x;
    const int tid = threadIdx.x;

    const float4* __restrict__ xp =
        reinterpret_cast<const float4*>(x + (size_t)row * HW);

    // ---------------- Phase A: ss + thread-max, minimal ops/element --------
    unsigned long long ssA = 0ull, ssB = 0ull;   // packed f32x2 accumulators (0,0)
    float mx0 = -CUDART_INF_F, mx1 = -CUDART_INF_F;

#pragma unroll
    for (int it = 0; it < NITER; it++) {
        float4 v = xp[tid + it * THREADS];
        unsigned long long p01, p23;
        asm("mov.b64 %0, {%1,%2};" : "=l"(p01) : "f"(v.x), "f"(v.y));
        asm("mov.b64 %0, {%1,%2};" : "=l"(p23) : "f"(v.z), "f"(v.w));
        asm("fma.rn.f32x2 %0, %1, %1, %0;" : "+l"(ssA) : "l"(p01));
        asm("fma.rn.f32x2 %0, %1, %1, %0;" : "+l"(ssB) : "l"(p23));
        mx0 = fmaxf(mx0, fmaxf(v.x, v.y));
        mx1 = fmaxf(mx1, fmaxf(v.z, v.w));
    }

    // unpack ss
    float sa0, sa1, sb0, sb1;
    asm("mov.b64 {%0,%1}, %2;" : "=f"(sa0), "=f"(sa1) : "l"(ssA));
    asm("mov.b64 {%0,%1}, %2;" : "=f"(sb0), "=f"(sb1) : "l"(ssB));
    float ssv = (sa0 + sa1) + (sb0 + sb1);

    const float    mymax = fmaxf(mx0, mx1);
    const unsigned key   = f2ord(mymax);

    // ---------------- shared state ----------------------------------------
    __shared__ unsigned long long cand_s[CAP];
    __shared__ float wss[THREADS / 32];
    __shared__ int ccnt;

    // warp reduce ss, stash per-warp sums; init candidate counter.
    const int lane = tid & 31;
    const int wid  = tid >> 5;
#pragma unroll
    for (int off = 16; off > 0; off >>= 1)
        ssv += __shfl_xor_sync(0xFFFFFFFFu, ssv, off);
    if (lane == 0) wss[wid] = ssv;
    if (tid == 0) ccnt = 0;
    // (visibility of wss/ccnt guaranteed by the barriers inside the radix loop)

    // ---------------- exact 16th-largest of 256 thread-maxes ---------------
    unsigned lo = 0;
#pragma unroll 1
    for (int bit = 31; bit >= 0; --bit) {
        unsigned candv = lo | (1u << bit);
        int cnt = __syncthreads_count(key >= candv);
        if (cnt >= KTOP) lo = candv;
    }
    const float tau = ord2f(lo);   // exact value of the 16th-largest thread-max

    // ---------------- Phase B: sparse rescan + candidate collection --------
    if (key >= lo) {               // ~16 of 256 threads
#pragma unroll
        for (int it = 0; it < NITER; it++) {
            float4 v = xp[tid + it * THREADS];
            int base = (tid + it * THREADS) * 4;
#pragma unroll
            for (int e = 0; e < 4; e++) {
                float f = (e == 0) ? v.x : (e == 1) ? v.y : (e == 2) ? v.z : v.w;
                if (f >= tau) {
                    unsigned long long kk =
                        ((unsigned long long)f2ord(f) << 32) |
                        (unsigned)(~(unsigned)(base + e));
                    int pos = atomicAdd(&ccnt, 1);
                    if (pos < CAP) cand_s[pos] = kk;
                }
            }
        }
    }
    __syncthreads();

    // ---------------- warp 0: select top-16 and write outputs --------------
    if (tid < 32) {
        int C = min(ccnt, CAP);    // guaranteed >= 16

        unsigned long long k[CAP / 32];
#pragma unroll
        for (int j = 0; j < CAP / 32; j++) {
            int i = tid + j * 32;
            k[j] = (i < C) ? cand_s[i] : 0ull;
        }

        // total sum of squares -> scale
        float tot = (tid < THREADS / 32) ? wss[tid] : 0.0f;
#pragma unroll
        for (int off = 16; off > 0; off >>= 1)
            tot += __shfl_xor_sync(0xFFFFFFFFu, tot, off);
        float scale = rsqrtf(fmaxf(tot, 1e-12f));

#pragma unroll 1
        for (int r = 0; r < KTOP; r++) {
            unsigned long long best = 0ull;
#pragma unroll
            for (int j = 0; j < CAP / 32; j++)
                if (k[j] > best) best = k[j];
#pragma unroll
            for (int off = 16; off > 0; off >>= 1) {
                unsigned long long o = __shfl_xor_sync(0xFFFFFFFFu, best, off);
                if (o > best) best = o;
            }
#pragma unroll
            for (int j = 0; j < CAP / 32; j++)
                if (k[j] == best) k[j] = 0ull;   // consume winner (keys unique)

            if (tid == 0) {
                float val = ord2f((unsigned)(best >> 32)) * scale;
                int idx = (int)(~(unsigned)(best & 0xFFFFFFFFull));
                out_val[(size_t)row * KTOP + r] = val;
                size_t cb = ((size_t)row * KTOP + r) * 2;
                out_coor[cb + 0] = (float)(idx >> 7);
                out_coor[cb + 1] = (float)(idx & (WDIM - 1));
            }
        }
    }
}

extern "C" void kernel_launch(void* const* d_in, const int* in_sizes, int n_in,
                              void* d_out, int out_size)
{
    const float* x = (const float*)d_in[0];
    int n = in_sizes[0];               // 16*256*128*128
    int rows = n / HW;                 // 4096

    float* out_val  = (float*)d_out;
    float* out_coor = out_val + (size_t)rows * KTOP;

    topk_l2_kernel<<<rows, THREADS>>>(x, out_val, out_coor);
}

// round 7
// speedup vs baseline: 8.3133x; 1.1108x over previous
#include <cuda_runtime.h>
#include <math_constants.h>

#define HW      16384
#define WDIM    128
#define KTOP    16
#define THREADS 256
#define NITER   (HW / 4 / THREADS)   // 16 float4s per thread
#define CAP     256                  // candidate buffer (expected ~30 used)
#define RADIX_LO_BIT 19              // stop bisection here (tau granularity <= 6.25%)

__device__ __forceinline__ unsigned f2ord(float f) {
    unsigned u = __float_as_uint(f);
    return u ^ ((unsigned)((int)u >> 31) | 0x80000000u);
}
__device__ __forceinline__ float ord2f(unsigned s) {
    unsigned u = (s & 0x80000000u) ? (s ^ 0x80000000u) : ~s;
    return __uint_as_float(u);
}

__global__ void __launch_bounds__(THREADS, 4)
topk_l2_kernel(const float* __restrict__ x,
               float* __restrict__ out_val,    // [rows,16]
               float2* __restrict__ out_coor)  // [rows,16] of (h,w)
{
    const int row = blockIdx.x;
    const int tid = threadIdx.x;

    const float4* __restrict__ xp =
        reinterpret_cast<const float4*>(x) + (size_t)row * (HW / 4);

    // ---------------- Phase A: ss + thread-max ----------------------------
    unsigned long long ssA = 0ull, ssB = 0ull;   // packed f32x2 accumulators
    float mx0 = -CUDART_INF_F, mx1 = -CUDART_INF_F;

#pragma unroll
    for (int it = 0; it < NITER; it++) {
        float4 v = xp[tid + it * THREADS];
        unsigned long long p01, p23;
        asm("mov.b64 %0, {%1,%2};" : "=l"(p01) : "f"(v.x), "f"(v.y));
        asm("mov.b64 %0, {%1,%2};" : "=l"(p23) : "f"(v.z), "f"(v.w));
        asm("fma.rn.f32x2 %0, %1, %1, %0;" : "+l"(ssA) : "l"(p01));
        asm("fma.rn.f32x2 %0, %1, %1, %0;" : "+l"(ssB) : "l"(p23));
        mx0 = fmaxf(mx0, fmaxf(v.x, v.y));
        mx1 = fmaxf(mx1, fmaxf(v.z, v.w));
    }

    float sa0, sa1, sb0, sb1;
    asm("mov.b64 {%0,%1}, %2;" : "=f"(sa0), "=f"(sa1) : "l"(ssA));
    asm("mov.b64 {%0,%1}, %2;" : "=f"(sb0), "=f"(sb1) : "l"(ssB));
    float ssv = (sa0 + sa1) + (sb0 + sb1);

    const float    mymax = fmaxf(mx0, mx1);
    const unsigned key   = f2ord(mymax);

    // ---------------- shared state ----------------------------------------
    __shared__ unsigned long long cand_s[CAP];
    __shared__ float wss[THREADS / 32];
    __shared__ int ccnt;

    const int lane = tid & 31;
    const int wid  = tid >> 5;
#pragma unroll
    for (int off = 16; off > 0; off >>= 1)
        ssv += __shfl_xor_sync(0xFFFFFFFFu, ssv, off);
    if (lane == 0) wss[wid] = ssv;
    if (tid == 0) ccnt = 0;
    // visibility of wss/ccnt is covered by the barriers in the radix loop

    // ------- truncated bisection: lower bound on 16th-largest thread-max ---
    unsigned lo = 0;
#pragma unroll 1
    for (int bit = 31; bit >= RADIX_LO_BIT; --bit) {
        unsigned candv = lo | (1u << bit);
        int cnt = __syncthreads_count(key >= candv);
        if (cnt >= KTOP) lo = candv;
    }
    // invariant: count(thread-maxes >= lo) >= 16  =>  tau <= 16th-largest element
    const float tau = ord2f(lo);

    // ---------------- Phase B: sparse rescan (L2 hits) ---------------------
    if (key >= lo) {               // ~16-30 of 256 threads
#pragma unroll
        for (int it = 0; it < NITER; it++) {
            float4 v = xp[tid + it * THREADS];
            int base = (tid + it * THREADS) * 4;
#pragma unroll
            for (int e = 0; e < 4; e++) {
                float f = (e == 0) ? v.x : (e == 1) ? v.y : (e == 2) ? v.z : v.w;
                if (f >= tau) {
                    unsigned long long kk =
                        ((unsigned long long)f2ord(f) << 32) |
                        (unsigned)(~(unsigned)(base + e));
                    int pos = atomicAdd(&ccnt, 1);
                    if (pos < CAP) cand_s[pos] = kk;
                }
            }
        }
    }
    __syncthreads();

    // ---------------- warp 0: smem-consume top-16 + write ------------------
    if (wid == 0) {
        const int C = min(ccnt, CAP);   // >= 16 guaranteed

        float tot = (lane < THREADS / 32) ? wss[lane] : 0.0f;
#pragma unroll
        for (int off = 4; off > 0; off >>= 1)
            tot += __shfl_xor_sync(0xFFFFFFFFu, tot, off);
        tot = __shfl_sync(0xFFFFFFFFu, tot, 0);
        const float scale = rsqrtf(fmaxf(tot, 1e-12f));

#pragma unroll 1
        for (int r = 0; r < KTOP; r++) {
            unsigned long long best = 0ull;
            for (int i = lane; i < C; i += 32) {
                unsigned long long c = cand_s[i];
                if (c > best) best = c;
            }
#pragma unroll
            for (int off = 16; off > 0; off >>= 1) {
                unsigned long long o = __shfl_xor_sync(0xFFFFFFFFu, best, off);
                if (o > best) best = o;
            }
            // consume winner (keys are unique: index embedded)
            for (int i = lane; i < C; i += 32)
                if (cand_s[i] == best) cand_s[i] = 0ull;

            if (lane == 0) {
                float val = ord2f((unsigned)(best >> 32)) * scale;
                int idx = (int)(~(unsigned)(best & 0xFFFFFFFFull));
                out_val[(size_t)row * KTOP + r] = val;
                out_coor[(size_t)row * KTOP + r] =
                    make_float2((float)(idx >> 7), (float)(idx & (WDIM - 1)));
            }
        }
    }
}

extern "C" void kernel_launch(void* const* d_in, const int* in_sizes, int n_in,
                              void* d_out, int out_size)
{
    const float* x = (const float*)d_in[0];
    int n = in_sizes[0];               // 16*256*128*128
    int rows = n / HW;                 // 4096

    float*  out_val  = (float*)d_out;
    float2* out_coor = (float2*)(out_val + (size_t)rows * KTOP);

    topk_l2_kernel<<<rows, THREADS>>>(x, out_val, out_coor);
}

// round 12
// speedup vs baseline: 11.8537x; 1.4259x over previous
#include <cuda_runtime.h>
#include <math_constants.h>

#define HW      16384
#define WDIM    128
#define KTOP    16
#define THREADS 256
#define NWARP   (THREADS / 32)
#define NITER   (HW / 4 / THREADS)   // 16 float4s per thread
#define CAP     1024                 // candidate buffer (expected ~22 used)

__device__ __forceinline__ unsigned f2ord(float f) {
    unsigned u = __float_as_uint(f);
    return u ^ ((unsigned)((int)u >> 31) | 0x80000000u);
}
__device__ __forceinline__ float ord2f(unsigned s) {
    unsigned u = (s & 0x80000000u) ? (s ^ 0x80000000u) : ~s;
    return __uint_as_float(u);
}

__global__ void __launch_bounds__(THREADS, 4)
topk_l2_kernel(const float* __restrict__ x,
               float* __restrict__ out_val,    // [rows,16]
               float2* __restrict__ out_coor)  // [rows,16] of (h,w)
{
    const int row = blockIdx.x;
    const int tid = threadIdx.x;
    const int lane = tid & 31;
    const int wid  = tid >> 5;

    const float4* __restrict__ xp =
        reinterpret_cast<const float4*>(x) + (size_t)row * (HW / 4);

    // ---------------- Phase A: ss + thread-max ----------------------------
    unsigned long long ssA = 0ull, ssB = 0ull;   // packed f32x2 accumulators
    float mx0 = -CUDART_INF_F, mx1 = -CUDART_INF_F;

#pragma unroll
    for (int it = 0; it < NITER; it++) {
        float4 v = xp[tid + it * THREADS];
        unsigned long long p01, p23;
        asm("mov.b64 %0, {%1,%2};" : "=l"(p01) : "f"(v.x), "f"(v.y));
        asm("mov.b64 %0, {%1,%2};" : "=l"(p23) : "f"(v.z), "f"(v.w));
        asm("fma.rn.f32x2 %0, %1, %1, %0;" : "+l"(ssA) : "l"(p01));
        asm("fma.rn.f32x2 %0, %1, %1, %0;" : "+l"(ssB) : "l"(p23));
        mx0 = fmaxf(mx0, fmaxf(v.x, v.y));
        mx1 = fmaxf(mx1, fmaxf(v.z, v.w));
    }

    float sa0, sa1, sb0, sb1;
    asm("mov.b64 {%0,%1}, %2;" : "=f"(sa0), "=f"(sa1) : "l"(ssA));
    asm("mov.b64 {%0,%1}, %2;" : "=f"(sb0), "=f"(sb1) : "l"(ssB));
    float ssv = (sa0 + sa1) + (sb0 + sb1);

    const unsigned key = f2ord(fmaxf(mx0, mx1));

    // ---- warp reduce: sum(ss) and top-2 of thread-max keys ----------------
    unsigned k1 = key, k2 = 0u;
#pragma unroll
    for (int off = 16; off > 0; off >>= 1) {
        ssv += __shfl_xor_sync(0xFFFFFFFFu, ssv, off);
        unsigned o1 = __shfl_xor_sync(0xFFFFFFFFu, k1, off);
        unsigned o2 = __shfl_xor_sync(0xFFFFFFFFu, k2, off);
        unsigned hi = max(k1, o1);
        unsigned se = max(min(k1, o1), max(k2, o2));
        k1 = hi; k2 = se;
    }

    // ---------------- shared state ----------------------------------------
    __shared__ unsigned long long cand_s[CAP];
    __shared__ float    wss[NWARP];
    __shared__ unsigned w2nd[NWARP];
    __shared__ int ccnt;

    if (lane == 0) { wss[wid] = ssv; w2nd[wid] = k2; }
    if (tid == 0) ccnt = 0;
    __syncthreads();   // barrier #1

    // tau = min over warps of (warp's 2nd-largest thread-max)
    // => >=2 elements per warp >= tau => >=16 elements >= tau (exactness)
    unsigned tau_ord = w2nd[0];
    float tot = wss[0];
#pragma unroll
    for (int w = 1; w < NWARP; w++) {
        tau_ord = min(tau_ord, w2nd[w]);
        tot += wss[w];
    }
    const float tau   = ord2f(tau_ord);
    const float scale = rsqrtf(fmaxf(tot, 1e-12f));

    // ---------------- Phase B: sparse rescan (L1/L2 hits) ------------------
    if (key >= tau_ord) {          // ~35 of 256 threads
#pragma unroll
        for (int it = 0; it < NITER; it++) {
            float4 v = xp[tid + it * THREADS];
            int base = (tid + it * THREADS) * 4;
#pragma unroll
            for (int e = 0; e < 4; e++) {
                float f = (e == 0) ? v.x : (e == 1) ? v.y : (e == 2) ? v.z : v.w;
                if (f >= tau) {
                    unsigned long long kk =
                        ((unsigned long long)f2ord(f) << 32) |
                        (unsigned)(~(unsigned)(base + e));
                    int pos = atomicAdd(&ccnt, 1);
                    if (pos < CAP) cand_s[pos] = kk;
                }
            }
        }
    }
    __syncthreads();   // barrier #2

    // ---------------- parallel rank-select + write -------------------------
    const int C = min(ccnt, CAP);   // >= 16 guaranteed
    for (int i = tid; i < C; i += THREADS) {
        unsigned long long mine = cand_s[i];
        int rank = 0;
        for (int j = 0; j < C; j++)
            rank += (cand_s[j] > mine);   // keys unique (index embedded)
        if (rank < KTOP) {
            float val = ord2f((unsigned)(mine >> 32)) * scale;
            int idx = (int)(~(unsigned)(mine & 0xFFFFFFFFull));
            out_val[(size_t)row * KTOP + rank] = val;
            out_coor[(size_t)row * KTOP + rank] =
                make_float2((float)(idx >> 7), (float)(idx & (WDIM - 1)));
        }
    }
}

extern "C" void kernel_launch(void* const* d_in, const int* in_sizes, int n_in,
                              void* d_out, int out_size)
{
    const float* x = (const float*)d_in[0];
    int n = in_sizes[0];               // 16*256*128*128
    int rows = n / HW;                 // 4096

    float*  out_val  = (float*)d_out;
    float2* out_coor = (float2*)(out_val + (size_t)rows * KTOP);

    topk_l2_kernel<<<rows, THREADS>>>(x, out_val, out_coor);
}